// round 1
// baseline (speedup 1.0000x reference)
#include <cuda_runtime.h>

// ---------------------------------------------------------------------------
// GINBlock: h = BN(relu( relu((x + scatter_add(x[src]->dst)) @ W1 + b1) @ W2 + b2 ))
// N=100000 nodes, D=H=128, E=3.2M edges, fp32 throughout.
// ---------------------------------------------------------------------------

#define GIN_N_MAX 100000
#define GIN_H 128

// Scratch (allocation-free rule: __device__ globals)
__device__ float g_h0[GIN_N_MAX * GIN_H];   // x + aggregation
__device__ float g_h1[GIN_N_MAX * GIN_H];   // after first MLP layer
__device__ float g_sum[GIN_H];
__device__ float g_sq[GIN_H];
__device__ float g_scale[GIN_H];
__device__ float g_shift[GIN_H];
__device__ int   g_is64;

// ---------------------------------------------------------------------------
// Detect whether edge_index is int64 or int32 (JAX may silently demote int64).
// If int64: the high 32-bit word of each element is 0 (indices in [0,1e5)).
// 16 consecutive high-words all zero => int64 (false-positive prob ~1e-80).
// ---------------------------------------------------------------------------
__global__ void detect_kernel(const unsigned* __restrict__ ei) {
    int allz = 1;
#pragma unroll
    for (int i = 0; i < 16; i++) allz &= (ei[2 * i + 1] == 0u);
    g_is64 = allz;
}

// h0 = x; zero BN accumulators
__global__ void init_kernel(const float4* __restrict__ x4, int total4) {
    int idx = blockIdx.x * blockDim.x + threadIdx.x;
    if (idx < total4) ((float4*)g_h0)[idx] = x4[idx];
    if (idx < GIN_H) { g_sum[idx] = 0.f; g_sq[idx] = 0.f; }
}

// One warp per edge: 32 lanes x float4 = 128 floats. Gather x[src], atomic-add
// into h0[dst]. x fits in L2 -> gather mostly L2 hits; atomics are LTS-bound.
__global__ void scatter_kernel(const float4* __restrict__ x4,
                               const void* __restrict__ ei, int E) {
    int idx = blockIdx.x * blockDim.x + threadIdx.x;
    int edge = idx >> 5;
    int lane = idx & 31;
    if (edge >= E) return;
    int s, d;
    if (g_is64) {
        const long long* p = (const long long*)ei;
        s = (int)__ldg(&p[edge]);
        d = (int)__ldg(&p[E + edge]);
    } else {
        const int* p = (const int*)ei;
        s = __ldg(&p[edge]);
        d = __ldg(&p[E + edge]);
    }
    float4 v = x4[s * 32 + lane];
    float* o = g_h0 + (d * 128 + lane * 4);
    atomicAdd(o + 0, v.x);
    atomicAdd(o + 1, v.y);
    atomicAdd(o + 2, v.z);
    atomicAdd(o + 3, v.w);
}

// ---------------------------------------------------------------------------
// Fused GEMM + bias + ReLU (+ optional column sum/sumsq for BatchNorm).
// C[128-row tile][128] = relu(A_tile[128x128] @ W[128x128] + bias)
// 256 threads, 8x8 register micro-tile per thread. 128 KB dynamic smem.
// ---------------------------------------------------------------------------
template <bool STATS>
__global__ void __launch_bounds__(256)
gemm_relu_kernel(const float* __restrict__ A, const float* __restrict__ W,
                 const float* __restrict__ bias, float* __restrict__ out, int N) {
    extern __shared__ float smem[];
    float* As = smem;             // 128 x 128 (row-major [m][k])
    float* Bs = smem + 16384;     // 128 x 128 (row-major [k][n])

    const int tid = threadIdx.x;
    const int row0 = blockIdx.x * 128;

    const float4* W4 = (const float4*)W;
    const float4* A4 = (const float4*)A;
    float4* Bs4 = (float4*)Bs;
    float4* As4 = (float4*)As;

#pragma unroll
    for (int i = 0; i < 16; i++) Bs4[tid + 256 * i] = W4[tid + 256 * i];
#pragma unroll
    for (int i = 0; i < 16; i++) {
        int l = tid + 256 * i;        // 0..4095 float4 slots
        int r = l >> 5;               // row within tile
        int gr = row0 + r;
        float4 v = make_float4(0.f, 0.f, 0.f, 0.f);
        if (gr < N) v = A4[gr * 32 + (l & 31)];
        As4[l] = v;
    }
    __syncthreads();

    const int tx = tid & 15, ty = tid >> 4;
    const int tn = tx * 8, tm = ty * 8;

    float acc[8][8];
#pragma unroll
    for (int i = 0; i < 8; i++)
#pragma unroll
        for (int j = 0; j < 8; j++) acc[i][j] = 0.f;

#pragma unroll 4
    for (int k = 0; k < 128; k++) {
        float a[8];
#pragma unroll
        for (int i = 0; i < 8; i++) a[i] = As[(tm + i) * 128 + k];
        float4 b0 = Bs4[(k * 128 + tn) >> 2];
        float4 b1 = Bs4[((k * 128 + tn) >> 2) + 1];
        float b[8] = {b0.x, b0.y, b0.z, b0.w, b1.x, b1.y, b1.z, b1.w};
#pragma unroll
        for (int i = 0; i < 8; i++)
#pragma unroll
            for (int j = 0; j < 8; j++)
                acc[i][j] = fmaf(a[i], b[j], acc[i][j]);
    }

    const float4* bias4 = (const float4*)bias;
    float4 bb0 = bias4[tn >> 2];
    float4 bb1 = bias4[(tn >> 2) + 1];
    float bv[8] = {bb0.x, bb0.y, bb0.z, bb0.w, bb1.x, bb1.y, bb1.z, bb1.w};
#pragma unroll
    for (int i = 0; i < 8; i++)
#pragma unroll
        for (int j = 0; j < 8; j++) {
            float v = acc[i][j] + bv[j];
            acc[i][j] = v > 0.f ? v : 0.f;
        }

    // store output tile
    float4* O4 = (float4*)out;
#pragma unroll
    for (int i = 0; i < 8; i++) {
        int gr = row0 + tm + i;
        if (gr < N) {
            O4[gr * 32 + (tn >> 2)] =
                make_float4(acc[i][0], acc[i][1], acc[i][2], acc[i][3]);
            O4[gr * 32 + (tn >> 2) + 1] =
                make_float4(acc[i][4], acc[i][5], acc[i][6], acc[i][7]);
        }
    }

    if (STATS) {
        // per-thread column partials (exclude out-of-range rows)
        float ps[8], pq[8];
#pragma unroll
        for (int j = 0; j < 8; j++) { ps[j] = 0.f; pq[j] = 0.f; }
#pragma unroll
        for (int i = 0; i < 8; i++) {
            if (row0 + tm + i < N) {
#pragma unroll
                for (int j = 0; j < 8; j++) {
                    ps[j] += acc[i][j];
                    pq[j] += acc[i][j] * acc[i][j];
                }
            }
        }
        __syncthreads();   // done reading As/Bs; reuse as reduction scratch
#pragma unroll
        for (int j = 0; j < 8; j++) {
            As[ty * 128 + tn + j] = ps[j];
            Bs[ty * 128 + tn + j] = pq[j];
        }
        __syncthreads();
        if (tid < 128) {
            float s = 0.f, q = 0.f;
#pragma unroll
            for (int t = 0; t < 16; t++) {
                s += As[t * 128 + tid];
                q += Bs[t * 128 + tid];
            }
            atomicAdd(&g_sum[tid], s);
            atomicAdd(&g_sq[tid], q);
        }
    }
}

__global__ void finalize_kernel(const float* __restrict__ gamma,
                                const float* __restrict__ beta, float invN) {
    int c = threadIdx.x;
    float mean = g_sum[c] * invN;
    float var = fmaf(-mean, mean, g_sq[c] * invN);
    float sc = gamma[c] * rsqrtf(var + 1e-5f);
    g_scale[c] = sc;
    g_shift[c] = fmaf(-mean, sc, beta[c]);
}

__global__ void apply_bn_kernel(float4* __restrict__ out, int total4) {
    int idx = blockIdx.x * blockDim.x + threadIdx.x;
    if (idx >= total4) return;
    int c = (idx & 31) * 4;
    float4 v = out[idx];
    v.x = fmaf(v.x, g_scale[c + 0], g_shift[c + 0]);
    v.y = fmaf(v.y, g_scale[c + 1], g_shift[c + 1]);
    v.z = fmaf(v.z, g_scale[c + 2], g_shift[c + 2]);
    v.w = fmaf(v.w, g_scale[c + 3], g_shift[c + 3]);
    out[idx] = v;
}

// ---------------------------------------------------------------------------
// Input order (metadata): x, edge_index, edge_attr, W1, b1, W2, b2, gamma, beta
// ---------------------------------------------------------------------------
extern "C" void kernel_launch(void* const* d_in, const int* in_sizes, int n_in,
                              void* d_out, int out_size) {
    const float* x     = (const float*)d_in[0];
    const void*  ei    = d_in[1];
    const float* W1    = (const float*)d_in[3];
    const float* b1    = (const float*)d_in[4];
    const float* W2    = (const float*)d_in[5];
    const float* b2    = (const float*)d_in[6];
    const float* gamma = (const float*)d_in[7];
    const float* beta  = (const float*)d_in[8];
    float* out = (float*)d_out;

    int N = in_sizes[0] / GIN_H;
    int E = in_sizes[1] / 2;

    const int SMEM = 2 * 128 * 128 * (int)sizeof(float);  // 128 KB
    cudaFuncSetAttribute(gemm_relu_kernel<false>,
                         cudaFuncAttributeMaxDynamicSharedMemorySize, SMEM);
    cudaFuncSetAttribute(gemm_relu_kernel<true>,
                         cudaFuncAttributeMaxDynamicSharedMemorySize, SMEM);

    int total4 = N * (GIN_H / 4);  // float4 elements of [N, 128]

    detect_kernel<<<1, 1>>>((const unsigned*)ei);
    init_kernel<<<(total4 + 255) / 256, 256>>>((const float4*)x, total4);

    long long scatter_items = (long long)E * 32;
    int scatter_blocks = (int)((scatter_items + 255) / 256);
    scatter_kernel<<<scatter_blocks, 256>>>((const float4*)x, ei, E);

    int gemm_blocks = (N + 127) / 128;
    float* h0;  cudaGetSymbolAddress((void**)&h0, g_h0);
    float* h1;  cudaGetSymbolAddress((void**)&h1, g_h1);

    gemm_relu_kernel<false><<<gemm_blocks, 256, SMEM>>>(h0, W1, b1, h1, N);
    gemm_relu_kernel<true ><<<gemm_blocks, 256, SMEM>>>(h1, W2, b2, out, N);

    finalize_kernel<<<1, 128>>>(gamma, beta, 1.0f / (float)N);
    apply_bn_kernel<<<(total4 + 255) / 256, 256>>>((float4*)out, total4);
}

// round 3
// speedup vs baseline: 1.7833x; 1.7833x over previous
#include <cuda_runtime.h>

// ---------------------------------------------------------------------------
// GINBlock: h = BN(relu( relu((x + scatter_add(x[src]->dst)) @ W1 + b1) @ W2 + b2 ))
// N=100000 nodes, D=H=128, E=3.2M edges, fp32 throughout.
// R3 (resubmit of R2; prior round died to container infra failure):
//   - red.global.add.v4.f32 scatter (4x fewer LTS atomic ops)
//   - GEMM: W resident + double-buffered A chunks -> 80KB smem, 2 CTAs/SM
// ---------------------------------------------------------------------------

#define GIN_N_MAX 100000
#define GIN_H 128

__device__ float g_h0[GIN_N_MAX * GIN_H];   // x + aggregation
__device__ float g_h1[GIN_N_MAX * GIN_H];   // after first MLP layer
__device__ float g_sum[GIN_H];
__device__ float g_sq[GIN_H];
__device__ float g_scale[GIN_H];
__device__ float g_shift[GIN_H];
__device__ int   g_is64;

// ---------------------------------------------------------------------------
// Detect int64 vs int32 edge_index (JAX may silently demote int64 to int32).
// Indices < 1e5, so int64 => high word of each element is 0.
// ---------------------------------------------------------------------------
__global__ void detect_kernel(const unsigned* __restrict__ ei) {
    int allz = 1;
#pragma unroll
    for (int i = 0; i < 16; i++) allz &= (ei[2 * i + 1] == 0u);
    g_is64 = allz;
}

// h0 = x; zero BN accumulators
__global__ void init_kernel(const float4* __restrict__ x4, int total4) {
    int idx = blockIdx.x * blockDim.x + threadIdx.x;
    if (idx < total4) ((float4*)g_h0)[idx] = x4[idx];
    if (idx < GIN_H) { g_sum[idx] = 0.f; g_sq[idx] = 0.f; }
}

// One warp per edge: 32 lanes x float4 = 128 floats. Gather x[src], vector
// reduce-add into h0[dst]. 1 RED.v4 per lane instead of 4 scalar REDs.
__global__ void scatter_kernel(const float4* __restrict__ x4,
                               const void* __restrict__ ei, int E) {
    int idx = blockIdx.x * blockDim.x + threadIdx.x;
    int edge = idx >> 5;
    int lane = idx & 31;
    if (edge >= E) return;
    int s, d;
    if (g_is64) {
        const long long* p = (const long long*)ei;
        s = (int)__ldg(&p[edge]);
        d = (int)__ldg(&p[E + edge]);
    } else {
        const int* p = (const int*)ei;
        s = __ldg(&p[edge]);
        d = __ldg(&p[E + edge]);
    }
    float4 v = x4[s * 32 + lane];
    float* o = g_h0 + (d * 128 + lane * 4);
    asm volatile("red.global.add.v4.f32 [%0], {%1, %2, %3, %4};"
                 :: "l"(o), "f"(v.x), "f"(v.y), "f"(v.z), "f"(v.w)
                 : "memory");
}

// ---------------------------------------------------------------------------
// Fused GEMM + bias + ReLU (+ optional column sum/sumsq for BatchNorm).
// C[128-row tile][128] = relu(A_tile @ W + bias).  W (128x128, 64KB) resident
// in smem; A streamed in 128x16 double-buffered chunks (2 x 8KB). 80KB smem
// total -> 2 CTAs/SM. 256 threads, 8x8 register micro-tile.
// ---------------------------------------------------------------------------
#define GEMM_SMEM_FLOATS (16384 + 2 * 2048)

template <bool STATS>
__global__ void __launch_bounds__(256, 2)
gemm_relu_kernel(const float* __restrict__ A, const float* __restrict__ W,
                 const float* __restrict__ bias, float* __restrict__ out, int N) {
    extern __shared__ float smem[];
    float* Bs = smem;                  // 128 x 128  [k][n]
    float* As = smem + 16384;          // 2 buffers of 128 x 16 [m][k']

    const int tid = threadIdx.x;
    const int row0 = blockIdx.x * 128;

    const float4* W4 = (const float4*)W;
    const float4* A4 = (const float4*)A;
    float4* Bs4 = (float4*)Bs;
    float4* As4 = (float4*)As;

#pragma unroll
    for (int i = 0; i < 16; i++) Bs4[tid + 256 * i] = W4[tid + 256 * i];

    // Chunk layout: 128 rows x 16 k = 512 float4 (4 float4 per row).
    // Each thread handles 2 float4 slots: s0 = tid*2, s0+1.
    const int s0 = tid * 2;
    const int ar0 = s0 >> 2, aq0 = s0 & 3;        // row, float4-within-row
    const int ar1 = (s0 + 1) >> 2, aq1 = (s0 + 1) & 3;

    // load chunk 0 into buffer 0
    {
        float4 r0 = make_float4(0.f, 0.f, 0.f, 0.f), r1 = r0;
        if (row0 + ar0 < N) r0 = A4[(row0 + ar0) * 32 + aq0];
        if (row0 + ar1 < N) r1 = A4[(row0 + ar1) * 32 + aq1];
        As4[ar0 * 4 + aq0] = r0;
        As4[ar1 * 4 + aq1] = r1;
    }
    __syncthreads();

    const int tx = tid & 15, ty = tid >> 4;
    const int tn = tx * 8, tm = ty * 8;

    float acc[8][8];
#pragma unroll
    for (int i = 0; i < 8; i++)
#pragma unroll
        for (int j = 0; j < 8; j++) acc[i][j] = 0.f;

    for (int kc = 0; kc < 8; kc++) {
        const int buf = kc & 1;
        float4 r0, r1;
        if (kc < 7) {   // prefetch next chunk into registers
            r0 = make_float4(0.f, 0.f, 0.f, 0.f); r1 = r0;
            if (row0 + ar0 < N) r0 = A4[(row0 + ar0) * 32 + (kc + 1) * 4 + aq0];
            if (row0 + ar1 < N) r1 = A4[(row0 + ar1) * 32 + (kc + 1) * 4 + aq1];
        }
        const float* Ab = As + buf * 2048;
#pragma unroll
        for (int k = 0; k < 16; k++) {
            float a[8];
#pragma unroll
            for (int i = 0; i < 8; i++) a[i] = Ab[(tm + i) * 16 + k];
            int boff = ((kc * 16 + k) * 128 + tn) >> 2;
            float4 b0 = Bs4[boff];
            float4 b1 = Bs4[boff + 1];
            float b[8] = {b0.x, b0.y, b0.z, b0.w, b1.x, b1.y, b1.z, b1.w};
#pragma unroll
            for (int i = 0; i < 8; i++)
#pragma unroll
                for (int j = 0; j < 8; j++)
                    acc[i][j] = fmaf(a[i], b[j], acc[i][j]);
        }
        if (kc < 7) {
            float4* Anext = As4 + ((kc + 1) & 1) * 512;
            Anext[ar0 * 4 + aq0] = r0;
            Anext[ar1 * 4 + aq1] = r1;
            __syncthreads();
        }
    }

    const float4* bias4 = (const float4*)bias;
    float4 bb0 = bias4[tn >> 2];
    float4 bb1 = bias4[(tn >> 2) + 1];
    float bv[8] = {bb0.x, bb0.y, bb0.z, bb0.w, bb1.x, bb1.y, bb1.z, bb1.w};
#pragma unroll
    for (int i = 0; i < 8; i++)
#pragma unroll
        for (int j = 0; j < 8; j++) {
            float v = acc[i][j] + bv[j];
            acc[i][j] = v > 0.f ? v : 0.f;
        }

    float4* O4 = (float4*)out;
#pragma unroll
    for (int i = 0; i < 8; i++) {
        int gr = row0 + tm + i;
        if (gr < N) {
            O4[gr * 32 + (tn >> 2)] =
                make_float4(acc[i][0], acc[i][1], acc[i][2], acc[i][3]);
            O4[gr * 32 + (tn >> 2) + 1] =
                make_float4(acc[i][4], acc[i][5], acc[i][6], acc[i][7]);
        }
    }

    if (STATS) {
        // column partials -> smem (reuse Bs) -> global atomics
        float ps[8], pq[8];
#pragma unroll
        for (int j = 0; j < 8; j++) { ps[j] = 0.f; pq[j] = 0.f; }
#pragma unroll
        for (int i = 0; i < 8; i++) {
            if (row0 + tm + i < N) {
#pragma unroll
                for (int j = 0; j < 8; j++) {
                    ps[j] += acc[i][j];
                    pq[j] += acc[i][j] * acc[i][j];
                }
            }
        }
        __syncthreads();   // done with Bs as weights
        float* S = Bs;          // 16 x 128
        float* Q = Bs + 2048;   // 16 x 128
#pragma unroll
        for (int j = 0; j < 8; j++) {
            S[ty * 128 + tn + j] = ps[j];
            Q[ty * 128 + tn + j] = pq[j];
        }
        __syncthreads();
        if (tid < 128) {
            float s = 0.f, q = 0.f;
#pragma unroll
            for (int t = 0; t < 16; t++) {
                s += S[t * 128 + tid];
                q += Q[t * 128 + tid];
            }
            atomicAdd(&g_sum[tid], s);
            atomicAdd(&g_sq[tid], q);
        }
    }
}

__global__ void finalize_kernel(const float* __restrict__ gamma,
                                const float* __restrict__ beta, float invN) {
    int c = threadIdx.x;
    float mean = g_sum[c] * invN;
    float var = fmaf(-mean, mean, g_sq[c] * invN);
    float sc = gamma[c] * rsqrtf(var + 1e-5f);
    g_scale[c] = sc;
    g_shift[c] = fmaf(-mean, sc, beta[c]);
}

__global__ void apply_bn_kernel(float4* __restrict__ out, int total4) {
    int idx = blockIdx.x * blockDim.x + threadIdx.x;
    if (idx >= total4) return;
    int c = (idx & 31) * 4;
    float4 v = out[idx];
    v.x = fmaf(v.x, g_scale[c + 0], g_shift[c + 0]);
    v.y = fmaf(v.y, g_scale[c + 1], g_shift[c + 1]);
    v.z = fmaf(v.z, g_scale[c + 2], g_shift[c + 2]);
    v.w = fmaf(v.w, g_scale[c + 3], g_shift[c + 3]);
    out[idx] = v;
}

// ---------------------------------------------------------------------------
// Input order: x, edge_index, edge_attr, W1, b1, W2, b2, gamma, beta
// ---------------------------------------------------------------------------
extern "C" void kernel_launch(void* const* d_in, const int* in_sizes, int n_in,
                              void* d_out, int out_size) {
    const float* x     = (const float*)d_in[0];
    const void*  ei    = d_in[1];
    const float* W1    = (const float*)d_in[3];
    const float* b1    = (const float*)d_in[4];
    const float* W2    = (const float*)d_in[5];
    const float* b2    = (const float*)d_in[6];
    const float* gamma = (const float*)d_in[7];
    const float* beta  = (const float*)d_in[8];
    float* out = (float*)d_out;

    int N = in_sizes[0] / GIN_H;
    int E = in_sizes[1] / 2;

    const int SMEM = GEMM_SMEM_FLOATS * (int)sizeof(float);  // 80 KB
    cudaFuncSetAttribute(gemm_relu_kernel<false>,
                         cudaFuncAttributeMaxDynamicSharedMemorySize, SMEM);
    cudaFuncSetAttribute(gemm_relu_kernel<true>,
                         cudaFuncAttributeMaxDynamicSharedMemorySize, SMEM);

    int total4 = N * (GIN_H / 4);

    detect_kernel<<<1, 1>>>((const unsigned*)ei);
    init_kernel<<<(total4 + 255) / 256, 256>>>((const float4*)x, total4);

    long long scatter_items = (long long)E * 32;
    int scatter_blocks = (int)((scatter_items + 255) / 256);
    scatter_kernel<<<scatter_blocks, 256>>>((const float4*)x, ei, E);

    int gemm_blocks = (N + 127) / 128;
    float* h0;  cudaGetSymbolAddress((void**)&h0, g_h0);
    float* h1;  cudaGetSymbolAddress((void**)&h1, g_h1);

    gemm_relu_kernel<false><<<gemm_blocks, 256, SMEM>>>(h0, W1, b1, h1, N);
    gemm_relu_kernel<true ><<<gemm_blocks, 256, SMEM>>>(h1, W2, b2, out, N);

    finalize_kernel<<<1, 128>>>(gamma, beta, 1.0f / (float)N);
    apply_bn_kernel<<<(total4 + 255) / 256, 256>>>((float4*)out, total4);
}

// round 4
// speedup vs baseline: 2.0627x; 1.1567x over previous
#include <cuda_runtime.h>

// ---------------------------------------------------------------------------
// GINBlock: h = BN(relu( relu((x + segsum(x[src]->dst)) @ W1 + b1) @ W2 + b2 ))
// N=100000, D=H=128, E=3.2M, fp32.
// R4: (1) GEMM inner loop on packed fma.rn.f32x2 (2 FMA/issue);
//     (2) scatter-atomics replaced by counting-sort -> CSR warp-per-node
//         gather-sum (kills 1.64GB of fp32 RED traffic).
// ---------------------------------------------------------------------------

#define GIN_N_MAX 100000
#define GIN_H 128
#define GIN_E_MAX 3200000

__device__ float g_h0[GIN_N_MAX * GIN_H];
__device__ float g_h1[GIN_N_MAX * GIN_H];
__device__ int   g_deg[GIN_N_MAX];
__device__ int   g_off[GIN_N_MAX + 1];
__device__ int   g_cursor[GIN_N_MAX];
__device__ int   g_srcs[GIN_E_MAX];
__device__ float g_sum[GIN_H];
__device__ float g_sq[GIN_H];
__device__ float g_scale[GIN_H];
__device__ float g_shift[GIN_H];
__device__ int   g_is64;

// ---------------------------------------------------------------------------
// int64 vs int32 edge_index detection (indices < 1e5 -> int64 high words = 0)
// ---------------------------------------------------------------------------
__global__ void detect_kernel(const unsigned* __restrict__ ei) {
    int allz = 1;
#pragma unroll
    for (int i = 0; i < 16; i++) allz &= (ei[2 * i + 1] == 0u);
    g_is64 = allz;
}

__global__ void zero_kernel(int N) {
    int idx = blockIdx.x * blockDim.x + threadIdx.x;
    if (idx < N) g_deg[idx] = 0;
    if (idx < GIN_H) { g_sum[idx] = 0.f; g_sq[idx] = 0.f; }
}

__global__ void hist_kernel(const void* __restrict__ ei, int E) {
    int e = blockIdx.x * blockDim.x + threadIdx.x;
    if (e >= E) return;
    int d = g_is64 ? (int)__ldg(&((const long long*)ei)[E + e])
                   : __ldg(&((const int*)ei)[E + e]);
    atomicAdd(&g_deg[d], 1);
}

// One-block exclusive scan over g_deg -> g_off (and cursor copy).
#define SCAN_T 1024
__global__ void __launch_bounds__(SCAN_T)
scan_kernel(int N) {
    __shared__ int sums[SCAN_T];
    int t = threadIdx.x;
    int C = (N + SCAN_T - 1) / SCAN_T;
    int beg = t * C, end = min(N, beg + C);
    int s = 0;
    for (int i = beg; i < end; i++) s += g_deg[i];
    sums[t] = s;
    __syncthreads();
    for (int d = 1; d < SCAN_T; d <<= 1) {
        int v = sums[t];
        int u = (t >= d) ? sums[t - d] : 0;
        __syncthreads();
        sums[t] = v + u;
        __syncthreads();
    }
    int run = (t > 0) ? sums[t - 1] : 0;
    for (int i = beg; i < end; i++) {
        g_off[i] = run;
        g_cursor[i] = run;
        run += g_deg[i];
    }
    if (t == SCAN_T - 1) g_off[N] = sums[SCAN_T - 1];
}

__global__ void permute_kernel(const void* __restrict__ ei, int E) {
    int e = blockIdx.x * blockDim.x + threadIdx.x;
    if (e >= E) return;
    int s, d;
    if (g_is64) {
        const long long* p = (const long long*)ei;
        s = (int)__ldg(&p[e]);
        d = (int)__ldg(&p[E + e]);
    } else {
        const int* p = (const int*)ei;
        s = __ldg(&p[e]);
        d = __ldg(&p[E + e]);
    }
    int pos = atomicAdd(&g_cursor[d], 1);
    g_srcs[pos] = s;
}

// Warp per node: acc = x[node] + sum over CSR segment of x[src].
// Lanes cooperatively stage 32 src indices, broadcast via shfl.
__global__ void aggregate_kernel(const float4* __restrict__ x4, int N) {
    int idx = blockIdx.x * blockDim.x + threadIdx.x;
    int node = idx >> 5;
    int lane = idx & 31;
    if (node >= N) return;
    int beg = g_off[node], end = g_off[node + 1];
    float4 acc = x4[node * 32 + lane];
    int e = beg;
    while (e < end) {
        int cnt = min(32, end - e);
        int myidx = (lane < cnt) ? __ldg(&g_srcs[e + lane]) : 0;
#pragma unroll 4
        for (int j = 0; j < cnt; j++) {
            int s = __shfl_sync(0xffffffffu, myidx, j);
            float4 v = x4[s * 32 + lane];
            acc.x += v.x; acc.y += v.y; acc.z += v.z; acc.w += v.w;
        }
        e += cnt;
    }
    ((float4*)g_h0)[node * 32 + lane] = acc;
}

// ---------------------------------------------------------------------------
// GEMM + bias + ReLU (+ BN stats) on packed fp32x2 FMAs.
// ---------------------------------------------------------------------------
typedef unsigned long long ull;

__device__ __forceinline__ void ffma2(ull& acc, ull a2, ull b2) {
    asm("fma.rn.f32x2 %0, %1, %2, %0;" : "+l"(acc) : "l"(a2), "l"(b2));
}
__device__ __forceinline__ ull dup2(float a) {
    ull r;
    asm("mov.b64 %0, {%1, %1};" : "=l"(r) : "f"(a));
    return r;
}
__device__ __forceinline__ void unpack2(ull p, float& lo, float& hi) {
    asm("mov.b64 {%0, %1}, %2;" : "=f"(lo), "=f"(hi) : "l"(p));
}

#define GEMM_SMEM_FLOATS (16384 + 2 * 2048)

template <bool STATS>
__global__ void __launch_bounds__(256, 2)
gemm_relu_kernel(const float* __restrict__ A, const float* __restrict__ W,
                 const float* __restrict__ bias, float* __restrict__ out, int N) {
    extern __shared__ float smem[];
    float* Bs = smem;                  // 128 x 128  [k][n]
    float* As = smem + 16384;          // 2 x (128 x 16) [m][k']

    const int tid = threadIdx.x;
    const int row0 = blockIdx.x * 128;

    const float4* W4 = (const float4*)W;
    const float4* A4 = (const float4*)A;
    float4* Bs4 = (float4*)Bs;
    float4* As4 = (float4*)As;

#pragma unroll
    for (int i = 0; i < 16; i++) Bs4[tid + 256 * i] = W4[tid + 256 * i];

    const int s0 = tid * 2;
    const int ar0 = s0 >> 2, aq0 = s0 & 3;
    const int ar1 = (s0 + 1) >> 2, aq1 = (s0 + 1) & 3;

    {
        float4 r0 = make_float4(0.f, 0.f, 0.f, 0.f), r1 = r0;
        if (row0 + ar0 < N) r0 = A4[(row0 + ar0) * 32 + aq0];
        if (row0 + ar1 < N) r1 = A4[(row0 + ar1) * 32 + aq1];
        As4[ar0 * 4 + aq0] = r0;
        As4[ar1 * 4 + aq1] = r1;
    }
    __syncthreads();

    const int tx = tid & 15, ty = tid >> 4;
    const int tn = tx * 8, tm = ty * 8;

    ull acc2[8][4];
#pragma unroll
    for (int i = 0; i < 8; i++)
#pragma unroll
        for (int j = 0; j < 4; j++) acc2[i][j] = 0ull;

    const ulonglong2* Bsu = (const ulonglong2*)Bs;

    for (int kc = 0; kc < 8; kc++) {
        const int buf = kc & 1;
        float4 r0, r1;
        if (kc < 7) {
            r0 = make_float4(0.f, 0.f, 0.f, 0.f); r1 = r0;
            if (row0 + ar0 < N) r0 = A4[(row0 + ar0) * 32 + (kc + 1) * 4 + aq0];
            if (row0 + ar1 < N) r1 = A4[(row0 + ar1) * 32 + (kc + 1) * 4 + aq1];
        }
        const float4* Ab4 = (const float4*)(As + buf * 2048);
#pragma unroll
        for (int k4 = 0; k4 < 4; k4++) {
            float4 av[8];
#pragma unroll
            for (int i = 0; i < 8; i++) av[i] = Ab4[(tm + i) * 4 + k4];
#pragma unroll
            for (int kk = 0; kk < 4; kk++) {
                const int k = kc * 16 + k4 * 4 + kk;
                const int boff = (k * 128 + tn) >> 2;
                ulonglong2 bA = Bsu[boff];      // (b0,b1),(b2,b3)
                ulonglong2 bB = Bsu[boff + 1];  // (b4,b5),(b6,b7)
#pragma unroll
                for (int i = 0; i < 8; i++) {
                    float a = (kk == 0) ? av[i].x : (kk == 1) ? av[i].y
                             : (kk == 2) ? av[i].z : av[i].w;
                    ull a2 = dup2(a);
                    ffma2(acc2[i][0], a2, bA.x);
                    ffma2(acc2[i][1], a2, bA.y);
                    ffma2(acc2[i][2], a2, bB.x);
                    ffma2(acc2[i][3], a2, bB.y);
                }
            }
        }
        if (kc < 7) {
            float4* Anext = As4 + ((kc + 1) & 1) * 512;
            Anext[ar0 * 4 + aq0] = r0;
            Anext[ar1 * 4 + aq1] = r1;
            __syncthreads();
        }
    }

    float acc[8][8];
#pragma unroll
    for (int i = 0; i < 8; i++)
#pragma unroll
        for (int j = 0; j < 4; j++)
            unpack2(acc2[i][j], acc[i][2 * j], acc[i][2 * j + 1]);

    const float4* bias4 = (const float4*)bias;
    float4 bb0 = bias4[tn >> 2];
    float4 bb1 = bias4[(tn >> 2) + 1];
    float bv[8] = {bb0.x, bb0.y, bb0.z, bb0.w, bb1.x, bb1.y, bb1.z, bb1.w};
#pragma unroll
    for (int i = 0; i < 8; i++)
#pragma unroll
        for (int j = 0; j < 8; j++) {
            float v = acc[i][j] + bv[j];
            acc[i][j] = v > 0.f ? v : 0.f;
        }

    float4* O4 = (float4*)out;
#pragma unroll
    for (int i = 0; i < 8; i++) {
        int gr = row0 + tm + i;
        if (gr < N) {
            O4[gr * 32 + (tn >> 2)] =
                make_float4(acc[i][0], acc[i][1], acc[i][2], acc[i][3]);
            O4[gr * 32 + (tn >> 2) + 1] =
                make_float4(acc[i][4], acc[i][5], acc[i][6], acc[i][7]);
        }
    }

    if (STATS) {
        float ps[8], pq[8];
#pragma unroll
        for (int j = 0; j < 8; j++) { ps[j] = 0.f; pq[j] = 0.f; }
#pragma unroll
        for (int i = 0; i < 8; i++) {
            if (row0 + tm + i < N) {
#pragma unroll
                for (int j = 0; j < 8; j++) {
                    ps[j] += acc[i][j];
                    pq[j] += acc[i][j] * acc[i][j];
                }
            }
        }
        __syncthreads();
        float* S = Bs;          // 16 x 128
        float* Q = Bs + 2048;   // 16 x 128
#pragma unroll
        for (int j = 0; j < 8; j++) {
            S[ty * 128 + tn + j] = ps[j];
            Q[ty * 128 + tn + j] = pq[j];
        }
        __syncthreads();
        if (tid < 128) {
            float s = 0.f, q = 0.f;
#pragma unroll
            for (int t = 0; t < 16; t++) {
                s += S[t * 128 + tid];
                q += Q[t * 128 + tid];
            }
            atomicAdd(&g_sum[tid], s);
            atomicAdd(&g_sq[tid], q);
        }
    }
}

__global__ void finalize_kernel(const float* __restrict__ gamma,
                                const float* __restrict__ beta, float invN) {
    int c = threadIdx.x;
    float mean = g_sum[c] * invN;
    float var = fmaf(-mean, mean, g_sq[c] * invN);
    float sc = gamma[c] * rsqrtf(var + 1e-5f);
    g_scale[c] = sc;
    g_shift[c] = fmaf(-mean, sc, beta[c]);
}

__global__ void apply_bn_kernel(float4* __restrict__ out, int total4) {
    int idx = blockIdx.x * blockDim.x + threadIdx.x;
    if (idx >= total4) return;
    int c = (idx & 31) * 4;
    float4 v = out[idx];
    v.x = fmaf(v.x, g_scale[c + 0], g_shift[c + 0]);
    v.y = fmaf(v.y, g_scale[c + 1], g_shift[c + 1]);
    v.z = fmaf(v.z, g_scale[c + 2], g_shift[c + 2]);
    v.w = fmaf(v.w, g_scale[c + 3], g_shift[c + 3]);
    out[idx] = v;
}

// ---------------------------------------------------------------------------
// Inputs: x, edge_index, edge_attr, W1, b1, W2, b2, gamma, beta
// ---------------------------------------------------------------------------
extern "C" void kernel_launch(void* const* d_in, const int* in_sizes, int n_in,
                              void* d_out, int out_size) {
    const float* x     = (const float*)d_in[0];
    const void*  ei    = d_in[1];
    const float* W1    = (const float*)d_in[3];
    const float* b1    = (const float*)d_in[4];
    const float* W2    = (const float*)d_in[5];
    const float* b2    = (const float*)d_in[6];
    const float* gamma = (const float*)d_in[7];
    const float* beta  = (const float*)d_in[8];
    float* out = (float*)d_out;

    int N = in_sizes[0] / GIN_H;
    int E = in_sizes[1] / 2;

    const int SMEM = GEMM_SMEM_FLOATS * (int)sizeof(float);  // 80 KB
    cudaFuncSetAttribute(gemm_relu_kernel<false>,
                         cudaFuncAttributeMaxDynamicSharedMemorySize, SMEM);
    cudaFuncSetAttribute(gemm_relu_kernel<true>,
                         cudaFuncAttributeMaxDynamicSharedMemorySize, SMEM);

    int total4 = N * (GIN_H / 4);
    int eb = (E + 255) / 256;

    detect_kernel<<<1, 1>>>((const unsigned*)ei);
    zero_kernel<<<(N + 255) / 256, 256>>>(N);
    hist_kernel<<<eb, 256>>>(ei, E);
    scan_kernel<<<1, SCAN_T>>>(N);
    permute_kernel<<<eb, 256>>>(ei, E);

    long long agg_items = (long long)N * 32;
    aggregate_kernel<<<(int)((agg_items + 255) / 256), 256>>>((const float4*)x, N);

    int gemm_blocks = (N + 127) / 128;
    float* h0;  cudaGetSymbolAddress((void**)&h0, g_h0);
    float* h1;  cudaGetSymbolAddress((void**)&h1, g_h1);

    gemm_relu_kernel<false><<<gemm_blocks, 256, SMEM>>>(h0, W1, b1, h1, N);
    gemm_relu_kernel<true ><<<gemm_blocks, 256, SMEM>>>(h1, W2, b2, out, N);

    finalize_kernel<<<1, 128>>>(gamma, beta, 1.0f / (float)N);
    apply_bn_kernel<<<(total4 + 255) / 256, 256>>>((float4*)out, total4);
}

// round 5
// speedup vs baseline: 2.8801x; 1.3963x over previous
#include <cuda_runtime.h>

// ---------------------------------------------------------------------------
// GINBlock: h = BN(relu( relu((x + segsum(x[src]->dst)) @ W1 + b1) @ W2 + b2 ))
// N=100000, D=H=128, E=3.2M, fp32.
// R5: replace 169us single-block scan with 3-phase parallel scan (~13us).
//     Keep: f32x2 GEMM, CSR counting-sort aggregate.
// ---------------------------------------------------------------------------

#define GIN_N_MAX 100000
#define GIN_H 128
#define GIN_E_MAX 3200000
#define SCAN_B 1024
#define SCAN_NB ((GIN_N_MAX + SCAN_B - 1) / SCAN_B)   // 98

__device__ float g_h0[GIN_N_MAX * GIN_H];
__device__ float g_h1[GIN_N_MAX * GIN_H];
__device__ int   g_deg[GIN_N_MAX];
__device__ int   g_off[GIN_N_MAX + 1];
__device__ int   g_cursor[GIN_N_MAX];
__device__ int   g_srcs[GIN_E_MAX];
__device__ int   g_bsum[SCAN_NB];
__device__ int   g_boff[SCAN_NB];
__device__ float g_sum[GIN_H];
__device__ float g_sq[GIN_H];
__device__ float g_scale[GIN_H];
__device__ float g_shift[GIN_H];
__device__ int   g_is64;

// ---------------------------------------------------------------------------
// int64 vs int32 edge_index detection (indices < 1e5 -> int64 high words = 0)
// ---------------------------------------------------------------------------
__global__ void detect_kernel(const unsigned* __restrict__ ei) {
    int allz = 1;
#pragma unroll
    for (int i = 0; i < 16; i++) allz &= (ei[2 * i + 1] == 0u);
    g_is64 = allz;
}

__global__ void zero_kernel(int N) {
    int idx = blockIdx.x * blockDim.x + threadIdx.x;
    if (idx < N) g_deg[idx] = 0;
    if (idx < GIN_H) { g_sum[idx] = 0.f; g_sq[idx] = 0.f; }
}

__global__ void hist_kernel(const void* __restrict__ ei, int E) {
    int e = blockIdx.x * blockDim.x + threadIdx.x;
    if (e >= E) return;
    int d = g_is64 ? (int)__ldg(&((const long long*)ei)[E + e])
                   : __ldg(&((const int*)ei)[E + e]);
    atomicAdd(&g_deg[d], 1);
}

// ---------------------------------------------------------------------------
// 3-phase parallel exclusive scan of g_deg[0..N) -> g_off, g_cursor
// ---------------------------------------------------------------------------
// Phase 1: per-block exclusive scan + block totals.
__global__ void __launch_bounds__(SCAN_B)
scan1_kernel(int N) {
    __shared__ int sh[SCAN_B];
    int t = threadIdx.x;
    int i = blockIdx.x * SCAN_B + t;
    int v = (i < N) ? g_deg[i] : 0;
    sh[t] = v;
    __syncthreads();
#pragma unroll
    for (int d = 1; d < SCAN_B; d <<= 1) {
        int u = (t >= d) ? sh[t - d] : 0;
        __syncthreads();
        sh[t] += u;
        __syncthreads();
    }
    if (i < N) g_off[i] = sh[t] - v;          // exclusive within block
    if (t == SCAN_B - 1) g_bsum[blockIdx.x] = sh[t];
}

// Phase 2: one block scans the block totals (NB <= 128).
__global__ void __launch_bounds__(128)
scan2_kernel(int NB) {
    __shared__ int sh[128];
    int t = threadIdx.x;
    int v = (t < NB) ? g_bsum[t] : 0;
    sh[t] = v;
    __syncthreads();
#pragma unroll
    for (int d = 1; d < 128; d <<= 1) {
        int u = (t >= d) ? sh[t - d] : 0;
        __syncthreads();
        sh[t] += u;
        __syncthreads();
    }
    if (t < NB) g_boff[t] = sh[t] - v;        // exclusive block offset
}

// Phase 3: add block offsets; init cursor; cap.
__global__ void scan3_kernel(int N, int E) {
    int i = blockIdx.x * blockDim.x + threadIdx.x;
    if (i >= N) return;
    int v = g_off[i] + g_boff[i >> 10];
    g_off[i] = v;
    g_cursor[i] = v;
    if (i == 0) g_off[N] = E;
}

__global__ void permute_kernel(const void* __restrict__ ei, int E) {
    int e = blockIdx.x * blockDim.x + threadIdx.x;
    if (e >= E) return;
    int s, d;
    if (g_is64) {
        const long long* p = (const long long*)ei;
        s = (int)__ldg(&p[e]);
        d = (int)__ldg(&p[E + e]);
    } else {
        const int* p = (const int*)ei;
        s = __ldg(&p[e]);
        d = __ldg(&p[E + e]);
    }
    int pos = atomicAdd(&g_cursor[d], 1);
    g_srcs[pos] = s;
}

// Warp per node: acc = x[node] + sum over CSR segment of x[src].
__global__ void aggregate_kernel(const float4* __restrict__ x4, int N) {
    int idx = blockIdx.x * blockDim.x + threadIdx.x;
    int node = idx >> 5;
    int lane = idx & 31;
    if (node >= N) return;
    int beg = g_off[node], end = g_off[node + 1];
    float4 acc = x4[node * 32 + lane];
    int e = beg;
    while (e < end) {
        int cnt = min(32, end - e);
        int myidx = (lane < cnt) ? __ldg(&g_srcs[e + lane]) : 0;
#pragma unroll 4
        for (int j = 0; j < cnt; j++) {
            int s = __shfl_sync(0xffffffffu, myidx, j);
            float4 v = x4[s * 32 + lane];
            acc.x += v.x; acc.y += v.y; acc.z += v.z; acc.w += v.w;
        }
        e += cnt;
    }
    ((float4*)g_h0)[node * 32 + lane] = acc;
}

// ---------------------------------------------------------------------------
// GEMM + bias + ReLU (+ BN stats) on packed fp32x2 FMAs.
// ---------------------------------------------------------------------------
typedef unsigned long long ull;

__device__ __forceinline__ void ffma2(ull& acc, ull a2, ull b2) {
    asm("fma.rn.f32x2 %0, %1, %2, %0;" : "+l"(acc) : "l"(a2), "l"(b2));
}
__device__ __forceinline__ ull dup2(float a) {
    ull r;
    asm("mov.b64 %0, {%1, %1};" : "=l"(r) : "f"(a));
    return r;
}
__device__ __forceinline__ void unpack2(ull p, float& lo, float& hi) {
    asm("mov.b64 {%0, %1}, %2;" : "=f"(lo), "=f"(hi) : "l"(p));
}

#define GEMM_SMEM_FLOATS (16384 + 2 * 2048)

template <bool STATS>
__global__ void __launch_bounds__(256, 2)
gemm_relu_kernel(const float* __restrict__ A, const float* __restrict__ W,
                 const float* __restrict__ bias, float* __restrict__ out, int N) {
    extern __shared__ float smem[];
    float* Bs = smem;                  // 128 x 128  [k][n]
    float* As = smem + 16384;          // 2 x (128 x 16) [m][k']

    const int tid = threadIdx.x;
    const int row0 = blockIdx.x * 128;

    const float4* W4 = (const float4*)W;
    const float4* A4 = (const float4*)A;
    float4* Bs4 = (float4*)Bs;
    float4* As4 = (float4*)As;

#pragma unroll
    for (int i = 0; i < 16; i++) Bs4[tid + 256 * i] = W4[tid + 256 * i];

    const int s0 = tid * 2;
    const int ar0 = s0 >> 2, aq0 = s0 & 3;
    const int ar1 = (s0 + 1) >> 2, aq1 = (s0 + 1) & 3;

    {
        float4 r0 = make_float4(0.f, 0.f, 0.f, 0.f), r1 = r0;
        if (row0 + ar0 < N) r0 = A4[(row0 + ar0) * 32 + aq0];
        if (row0 + ar1 < N) r1 = A4[(row0 + ar1) * 32 + aq1];
        As4[ar0 * 4 + aq0] = r0;
        As4[ar1 * 4 + aq1] = r1;
    }
    __syncthreads();

    const int tx = tid & 15, ty = tid >> 4;
    const int tn = tx * 8, tm = ty * 8;

    ull acc2[8][4];
#pragma unroll
    for (int i = 0; i < 8; i++)
#pragma unroll
        for (int j = 0; j < 4; j++) acc2[i][j] = 0ull;

    const ulonglong2* Bsu = (const ulonglong2*)Bs;

    for (int kc = 0; kc < 8; kc++) {
        const int buf = kc & 1;
        float4 r0, r1;
        if (kc < 7) {
            r0 = make_float4(0.f, 0.f, 0.f, 0.f); r1 = r0;
            if (row0 + ar0 < N) r0 = A4[(row0 + ar0) * 32 + (kc + 1) * 4 + aq0];
            if (row0 + ar1 < N) r1 = A4[(row0 + ar1) * 32 + (kc + 1) * 4 + aq1];
        }
        const float4* Ab4 = (const float4*)(As + buf * 2048);
#pragma unroll
        for (int k4 = 0; k4 < 4; k4++) {
            float4 av[8];
#pragma unroll
            for (int i = 0; i < 8; i++) av[i] = Ab4[(tm + i) * 4 + k4];
#pragma unroll
            for (int kk = 0; kk < 4; kk++) {
                const int k = kc * 16 + k4 * 4 + kk;
                const int boff = (k * 128 + tn) >> 2;
                ulonglong2 bA = Bsu[boff];
                ulonglong2 bB = Bsu[boff + 1];
#pragma unroll
                for (int i = 0; i < 8; i++) {
                    float a = (kk == 0) ? av[i].x : (kk == 1) ? av[i].y
                             : (kk == 2) ? av[i].z : av[i].w;
                    ull a2 = dup2(a);
                    ffma2(acc2[i][0], a2, bA.x);
                    ffma2(acc2[i][1], a2, bA.y);
                    ffma2(acc2[i][2], a2, bB.x);
                    ffma2(acc2[i][3], a2, bB.y);
                }
            }
        }
        if (kc < 7) {
            float4* Anext = As4 + ((kc + 1) & 1) * 512;
            Anext[ar0 * 4 + aq0] = r0;
            Anext[ar1 * 4 + aq1] = r1;
            __syncthreads();
        }
    }

    float acc[8][8];
#pragma unroll
    for (int i = 0; i < 8; i++)
#pragma unroll
        for (int j = 0; j < 4; j++)
            unpack2(acc2[i][j], acc[i][2 * j], acc[i][2 * j + 1]);

    const float4* bias4 = (const float4*)bias;
    float4 bb0 = bias4[tn >> 2];
    float4 bb1 = bias4[(tn >> 2) + 1];
    float bv[8] = {bb0.x, bb0.y, bb0.z, bb0.w, bb1.x, bb1.y, bb1.z, bb1.w};
#pragma unroll
    for (int i = 0; i < 8; i++)
#pragma unroll
        for (int j = 0; j < 8; j++) {
            float v = acc[i][j] + bv[j];
            acc[i][j] = v > 0.f ? v : 0.f;
        }

    float4* O4 = (float4*)out;
#pragma unroll
    for (int i = 0; i < 8; i++) {
        int gr = row0 + tm + i;
        if (gr < N) {
            O4[gr * 32 + (tn >> 2)] =
                make_float4(acc[i][0], acc[i][1], acc[i][2], acc[i][3]);
            O4[gr * 32 + (tn >> 2) + 1] =
                make_float4(acc[i][4], acc[i][5], acc[i][6], acc[i][7]);
        }
    }

    if (STATS) {
        float ps[8], pq[8];
#pragma unroll
        for (int j = 0; j < 8; j++) { ps[j] = 0.f; pq[j] = 0.f; }
#pragma unroll
        for (int i = 0; i < 8; i++) {
            if (row0 + tm + i < N) {
#pragma unroll
                for (int j = 0; j < 8; j++) {
                    ps[j] += acc[i][j];
                    pq[j] += acc[i][j] * acc[i][j];
                }
            }
        }
        __syncthreads();
        float* S = Bs;          // 16 x 128
        float* Q = Bs + 2048;   // 16 x 128
#pragma unroll
        for (int j = 0; j < 8; j++) {
            S[ty * 128 + tn + j] = ps[j];
            Q[ty * 128 + tn + j] = pq[j];
        }
        __syncthreads();
        if (tid < 128) {
            float s = 0.f, q = 0.f;
#pragma unroll
            for (int t = 0; t < 16; t++) {
                s += S[t * 128 + tid];
                q += Q[t * 128 + tid];
            }
            atomicAdd(&g_sum[tid], s);
            atomicAdd(&g_sq[tid], q);
        }
    }
}

__global__ void finalize_kernel(const float* __restrict__ gamma,
                                const float* __restrict__ beta, float invN) {
    int c = threadIdx.x;
    float mean = g_sum[c] * invN;
    float var = fmaf(-mean, mean, g_sq[c] * invN);
    float sc = gamma[c] * rsqrtf(var + 1e-5f);
    g_scale[c] = sc;
    g_shift[c] = fmaf(-mean, sc, beta[c]);
}

__global__ void apply_bn_kernel(float4* __restrict__ out, int total4) {
    int idx = blockIdx.x * blockDim.x + threadIdx.x;
    if (idx >= total4) return;
    int c = (idx & 31) * 4;
    float4 v = out[idx];
    v.x = fmaf(v.x, g_scale[c + 0], g_shift[c + 0]);
    v.y = fmaf(v.y, g_scale[c + 1], g_shift[c + 1]);
    v.z = fmaf(v.z, g_scale[c + 2], g_shift[c + 2]);
    v.w = fmaf(v.w, g_scale[c + 3], g_shift[c + 3]);
    out[idx] = v;
}

// ---------------------------------------------------------------------------
// Inputs: x, edge_index, edge_attr, W1, b1, W2, b2, gamma, beta
// ---------------------------------------------------------------------------
extern "C" void kernel_launch(void* const* d_in, const int* in_sizes, int n_in,
                              void* d_out, int out_size) {
    const float* x     = (const float*)d_in[0];
    const void*  ei    = d_in[1];
    const float* W1    = (const float*)d_in[3];
    const float* b1    = (const float*)d_in[4];
    const float* W2    = (const float*)d_in[5];
    const float* b2    = (const float*)d_in[6];
    const float* gamma = (const float*)d_in[7];
    const float* beta  = (const float*)d_in[8];
    float* out = (float*)d_out;

    int N = in_sizes[0] / GIN_H;
    int E = in_sizes[1] / 2;

    const int SMEM = GEMM_SMEM_FLOATS * (int)sizeof(float);  // 80 KB
    cudaFuncSetAttribute(gemm_relu_kernel<false>,
                         cudaFuncAttributeMaxDynamicSharedMemorySize, SMEM);
    cudaFuncSetAttribute(gemm_relu_kernel<true>,
                         cudaFuncAttributeMaxDynamicSharedMemorySize, SMEM);

    int total4 = N * (GIN_H / 4);
    int eb = (E + 255) / 256;
    int nb = (N + SCAN_B - 1) / SCAN_B;

    detect_kernel<<<1, 1>>>((const unsigned*)ei);
    zero_kernel<<<(N + 255) / 256, 256>>>(N);
    hist_kernel<<<eb, 256>>>(ei, E);
    scan1_kernel<<<nb, SCAN_B>>>(N);
    scan2_kernel<<<1, 128>>>(nb);
    scan3_kernel<<<(N + 255) / 256, 256>>>(N, E);
    permute_kernel<<<eb, 256>>>(ei, E);

    long long agg_items = (long long)N * 32;
    aggregate_kernel<<<(int)((agg_items + 255) / 256), 256>>>((const float4*)x, N);

    int gemm_blocks = (N + 127) / 128;
    float* h0;  cudaGetSymbolAddress((void**)&h0, g_h0);
    float* h1;  cudaGetSymbolAddress((void**)&h1, g_h1);

    gemm_relu_kernel<false><<<gemm_blocks, 256, SMEM>>>(h0, W1, b1, h1, N);
    gemm_relu_kernel<true ><<<gemm_blocks, 256, SMEM>>>(h1, W2, b2, out, N);

    finalize_kernel<<<1, 128>>>(gamma, beta, 1.0f / (float)N);
    apply_bn_kernel<<<(total4 + 255) / 256, 256>>>((float4*)out, total4);
}

// round 6
// speedup vs baseline: 3.0074x; 1.0442x over previous
#include <cuda_runtime.h>
#include <cuda_fp16.h>

// ---------------------------------------------------------------------------
// GINBlock: h = BN(relu( relu((x + segsum(x[src]->dst)) @ W1 + b1) @ W2 + b2 ))
// N=100000, D=H=128, E=3.2M, fp32.
// R6: aggregate gathers from an fp16 mirror of x (halves the 1.64GB L2-bound
//     gather traffic; fp32 accumulation, self term exact fp32).
//     Fold detect->zero, BN finalize->apply. Keep f32x2 GEMM + CSR sort.
// ---------------------------------------------------------------------------

#define GIN_N_MAX 100000
#define GIN_H 128
#define GIN_E_MAX 3200000
#define SCAN_B 1024
#define SCAN_NB ((GIN_N_MAX + SCAN_B - 1) / SCAN_B)   // 98

__device__ float  g_h0[GIN_N_MAX * GIN_H];
__device__ float  g_h1[GIN_N_MAX * GIN_H];
__device__ __half g_xh[GIN_N_MAX * GIN_H];       // fp16 mirror of x
__device__ int    g_deg[GIN_N_MAX];
__device__ int    g_off[GIN_N_MAX + 1];
__device__ int    g_cursor[GIN_N_MAX];
__device__ int    g_srcs[GIN_E_MAX];
__device__ int    g_bsum[SCAN_NB];
__device__ int    g_boff[SCAN_NB];
__device__ float  g_sum[GIN_H];
__device__ float  g_sq[GIN_H];
__device__ int    g_is64;

// zero degree array + BN accumulators; thread 0 of block 0 also runs the
// int64-vs-int32 edge_index sniff (indices < 1e5 -> int64 high words all 0).
__global__ void zero_kernel(const unsigned* __restrict__ ei, int N) {
    int idx = blockIdx.x * blockDim.x + threadIdx.x;
    if (idx < N) g_deg[idx] = 0;
    if (idx < GIN_H) { g_sum[idx] = 0.f; g_sq[idx] = 0.f; }
    if (idx == 0) {
        int allz = 1;
#pragma unroll
        for (int i = 0; i < 16; i++) allz &= (ei[2 * i + 1] == 0u);
        g_is64 = allz;
    }
}

// fp32 x -> fp16 mirror (half4 per thread)
__global__ void convert_kernel(const float4* __restrict__ x4, int total4) {
    int idx = blockIdx.x * blockDim.x + threadIdx.x;
    if (idx >= total4) return;
    float4 v = x4[idx];
    __half2 a = __floats2half2_rn(v.x, v.y);
    __half2 b = __floats2half2_rn(v.z, v.w);
    uint2 p;
    p.x = *(unsigned*)&a;
    p.y = *(unsigned*)&b;
    ((uint2*)g_xh)[idx] = p;
}

__global__ void hist_kernel(const void* __restrict__ ei, int E) {
    int e = blockIdx.x * blockDim.x + threadIdx.x;
    if (e >= E) return;
    int d = g_is64 ? (int)__ldg(&((const long long*)ei)[E + e])
                   : __ldg(&((const int*)ei)[E + e]);
    atomicAdd(&g_deg[d], 1);
}

// ---- 3-phase exclusive scan of g_deg -> g_off, g_cursor ----
__global__ void __launch_bounds__(SCAN_B)
scan1_kernel(int N) {
    __shared__ int sh[SCAN_B];
    int t = threadIdx.x;
    int i = blockIdx.x * SCAN_B + t;
    int v = (i < N) ? g_deg[i] : 0;
    sh[t] = v;
    __syncthreads();
#pragma unroll
    for (int d = 1; d < SCAN_B; d <<= 1) {
        int u = (t >= d) ? sh[t - d] : 0;
        __syncthreads();
        sh[t] += u;
        __syncthreads();
    }
    if (i < N) g_off[i] = sh[t] - v;
    if (t == SCAN_B - 1) g_bsum[blockIdx.x] = sh[t];
}

__global__ void __launch_bounds__(128)
scan2_kernel(int NB) {
    __shared__ int sh[128];
    int t = threadIdx.x;
    int v = (t < NB) ? g_bsum[t] : 0;
    sh[t] = v;
    __syncthreads();
#pragma unroll
    for (int d = 1; d < 128; d <<= 1) {
        int u = (t >= d) ? sh[t - d] : 0;
        __syncthreads();
        sh[t] += u;
        __syncthreads();
    }
    if (t < NB) g_boff[t] = sh[t] - v;
}

__global__ void scan3_kernel(int N, int E) {
    int i = blockIdx.x * blockDim.x + threadIdx.x;
    if (i >= N) return;
    int v = g_off[i] + g_boff[i >> 10];
    g_off[i] = v;
    g_cursor[i] = v;
    if (i == 0) g_off[N] = E;
}

__global__ void permute_kernel(const void* __restrict__ ei, int E) {
    int e = blockIdx.x * blockDim.x + threadIdx.x;
    if (e >= E) return;
    int s, d;
    if (g_is64) {
        const long long* p = (const long long*)ei;
        s = (int)__ldg(&p[e]);
        d = (int)__ldg(&p[E + e]);
    } else {
        const int* p = (const int*)ei;
        s = __ldg(&p[e]);
        d = __ldg(&p[E + e]);
    }
    int pos = atomicAdd(&g_cursor[d], 1);
    g_srcs[pos] = s;
}

// Warp per node: acc = x[node](fp32) + sum of fp16-mirror rows of neighbors.
// fp16 gather = 256B/edge (half the fp32 traffic); fp32 accumulation.
__global__ void aggregate_kernel(const float4* __restrict__ x4, int N) {
    int idx = blockIdx.x * blockDim.x + threadIdx.x;
    int node = idx >> 5;
    int lane = idx & 31;
    if (node >= N) return;
    int beg = g_off[node], end = g_off[node + 1];
    float4 acc = x4[node * 32 + lane];
    const uint2* xh = (const uint2*)g_xh;
    int e = beg;
    while (e < end) {
        int cnt = min(32, end - e);
        int myidx = (lane < cnt) ? __ldg(&g_srcs[e + lane]) : 0;
#pragma unroll 4
        for (int j = 0; j < cnt; j++) {
            int s = __shfl_sync(0xffffffffu, myidx, j);
            uint2 p = xh[s * 32 + lane];
            float2 f01 = __half22float2(*(__half2*)&p.x);
            float2 f23 = __half22float2(*(__half2*)&p.y);
            acc.x += f01.x; acc.y += f01.y; acc.z += f23.x; acc.w += f23.y;
        }
        e += cnt;
    }
    ((float4*)g_h0)[node * 32 + lane] = acc;
}

// ---------------------------------------------------------------------------
// GEMM + bias + ReLU (+ BN stats) on packed fp32x2 FMAs.
// ---------------------------------------------------------------------------
typedef unsigned long long ull;

__device__ __forceinline__ void ffma2(ull& acc, ull a2, ull b2) {
    asm("fma.rn.f32x2 %0, %1, %2, %0;" : "+l"(acc) : "l"(a2), "l"(b2));
}
__device__ __forceinline__ ull dup2(float a) {
    ull r;
    asm("mov.b64 %0, {%1, %1};" : "=l"(r) : "f"(a));
    return r;
}
__device__ __forceinline__ void unpack2(ull p, float& lo, float& hi) {
    asm("mov.b64 {%0, %1}, %2;" : "=f"(lo), "=f"(hi) : "l"(p));
}

#define GEMM_SMEM_FLOATS (16384 + 2 * 2048)

template <bool STATS>
__global__ void __launch_bounds__(256, 2)
gemm_relu_kernel(const float* __restrict__ A, const float* __restrict__ W,
                 const float* __restrict__ bias, float* __restrict__ out, int N) {
    extern __shared__ float smem[];
    float* Bs = smem;                  // 128 x 128  [k][n]
    float* As = smem + 16384;          // 2 x (128 x 16) [m][k']

    const int tid = threadIdx.x;
    const int row0 = blockIdx.x * 128;

    const float4* W4 = (const float4*)W;
    const float4* A4 = (const float4*)A;
    float4* Bs4 = (float4*)Bs;
    float4* As4 = (float4*)As;

#pragma unroll
    for (int i = 0; i < 16; i++) Bs4[tid + 256 * i] = W4[tid + 256 * i];

    const int s0 = tid * 2;
    const int ar0 = s0 >> 2, aq0 = s0 & 3;
    const int ar1 = (s0 + 1) >> 2, aq1 = (s0 + 1) & 3;

    {
        float4 r0 = make_float4(0.f, 0.f, 0.f, 0.f), r1 = r0;
        if (row0 + ar0 < N) r0 = A4[(row0 + ar0) * 32 + aq0];
        if (row0 + ar1 < N) r1 = A4[(row0 + ar1) * 32 + aq1];
        As4[ar0 * 4 + aq0] = r0;
        As4[ar1 * 4 + aq1] = r1;
    }
    __syncthreads();

    const int tx = tid & 15, ty = tid >> 4;
    const int tn = tx * 8, tm = ty * 8;

    ull acc2[8][4];
#pragma unroll
    for (int i = 0; i < 8; i++)
#pragma unroll
        for (int j = 0; j < 4; j++) acc2[i][j] = 0ull;

    const ulonglong2* Bsu = (const ulonglong2*)Bs;

    for (int kc = 0; kc < 8; kc++) {
        const int buf = kc & 1;
        float4 r0, r1;
        if (kc < 7) {
            r0 = make_float4(0.f, 0.f, 0.f, 0.f); r1 = r0;
            if (row0 + ar0 < N) r0 = A4[(row0 + ar0) * 32 + (kc + 1) * 4 + aq0];
            if (row0 + ar1 < N) r1 = A4[(row0 + ar1) * 32 + (kc + 1) * 4 + aq1];
        }
        const float4* Ab4 = (const float4*)(As + buf * 2048);
#pragma unroll
        for (int k4 = 0; k4 < 4; k4++) {
            float4 av[8];
#pragma unroll
            for (int i = 0; i < 8; i++) av[i] = Ab4[(tm + i) * 4 + k4];
#pragma unroll
            for (int kk = 0; kk < 4; kk++) {
                const int k = kc * 16 + k4 * 4 + kk;
                const int boff = (k * 128 + tn) >> 2;
                ulonglong2 bA = Bsu[boff];
                ulonglong2 bB = Bsu[boff + 1];
#pragma unroll
                for (int i = 0; i < 8; i++) {
                    float a = (kk == 0) ? av[i].x : (kk == 1) ? av[i].y
                             : (kk == 2) ? av[i].z : av[i].w;
                    ull a2 = dup2(a);
                    ffma2(acc2[i][0], a2, bA.x);
                    ffma2(acc2[i][1], a2, bA.y);
                    ffma2(acc2[i][2], a2, bB.x);
                    ffma2(acc2[i][3], a2, bB.y);
                }
            }
        }
        if (kc < 7) {
            float4* Anext = As4 + ((kc + 1) & 1) * 512;
            Anext[ar0 * 4 + aq0] = r0;
            Anext[ar1 * 4 + aq1] = r1;
            __syncthreads();
        }
    }

    float acc[8][8];
#pragma unroll
    for (int i = 0; i < 8; i++)
#pragma unroll
        for (int j = 0; j < 4; j++)
            unpack2(acc2[i][j], acc[i][2 * j], acc[i][2 * j + 1]);

    const float4* bias4 = (const float4*)bias;
    float4 bb0 = bias4[tn >> 2];
    float4 bb1 = bias4[(tn >> 2) + 1];
    float bv[8] = {bb0.x, bb0.y, bb0.z, bb0.w, bb1.x, bb1.y, bb1.z, bb1.w};
#pragma unroll
    for (int i = 0; i < 8; i++)
#pragma unroll
        for (int j = 0; j < 8; j++) {
            float v = acc[i][j] + bv[j];
            acc[i][j] = v > 0.f ? v : 0.f;
        }

    float4* O4 = (float4*)out;
#pragma unroll
    for (int i = 0; i < 8; i++) {
        int gr = row0 + tm + i;
        if (gr < N) {
            O4[gr * 32 + (tn >> 2)] =
                make_float4(acc[i][0], acc[i][1], acc[i][2], acc[i][3]);
            O4[gr * 32 + (tn >> 2) + 1] =
                make_float4(acc[i][4], acc[i][5], acc[i][6], acc[i][7]);
        }
    }

    if (STATS) {
        float ps[8], pq[8];
#pragma unroll
        for (int j = 0; j < 8; j++) { ps[j] = 0.f; pq[j] = 0.f; }
#pragma unroll
        for (int i = 0; i < 8; i++) {
            if (row0 + tm + i < N) {
#pragma unroll
                for (int j = 0; j < 8; j++) {
                    ps[j] += acc[i][j];
                    pq[j] += acc[i][j] * acc[i][j];
                }
            }
        }
        __syncthreads();
        float* S = Bs;          // 16 x 128
        float* Q = Bs + 2048;   // 16 x 128
#pragma unroll
        for (int j = 0; j < 8; j++) {
            S[ty * 128 + tn + j] = ps[j];
            Q[ty * 128 + tn + j] = pq[j];
        }
        __syncthreads();
        if (tid < 128) {
            float s = 0.f, q = 0.f;
#pragma unroll
            for (int t = 0; t < 16; t++) {
                s += S[t * 128 + tid];
                q += Q[t * 128 + tid];
            }
            atomicAdd(&g_sum[tid], s);
            atomicAdd(&g_sq[tid], q);
        }
    }
}

// BN apply with per-block recompute of scale/shift from the global sums
// (128 smem floats per block -- negligible redundant work, kills a kernel).
__global__ void apply_bn_kernel(float4* __restrict__ out,
                                const float* __restrict__ gamma,
                                const float* __restrict__ beta,
                                float invN, int total4) {
    __shared__ float s_scale[GIN_H], s_shift[GIN_H];
    int t = threadIdx.x;
    if (t < GIN_H) {
        float mean = g_sum[t] * invN;
        float var = fmaf(-mean, mean, g_sq[t] * invN);
        float sc = gamma[t] * rsqrtf(var + 1e-5f);
        s_scale[t] = sc;
        s_shift[t] = fmaf(-mean, sc, beta[t]);
    }
    __syncthreads();
    int idx = blockIdx.x * blockDim.x + t;
    if (idx >= total4) return;
    int c = (idx & 31) * 4;
    float4 v = out[idx];
    v.x = fmaf(v.x, s_scale[c + 0], s_shift[c + 0]);
    v.y = fmaf(v.y, s_scale[c + 1], s_shift[c + 1]);
    v.z = fmaf(v.z, s_scale[c + 2], s_shift[c + 2]);
    v.w = fmaf(v.w, s_scale[c + 3], s_shift[c + 3]);
    out[idx] = v;
}

// ---------------------------------------------------------------------------
// Inputs: x, edge_index, edge_attr, W1, b1, W2, b2, gamma, beta
// ---------------------------------------------------------------------------
extern "C" void kernel_launch(void* const* d_in, const int* in_sizes, int n_in,
                              void* d_out, int out_size) {
    const float* x     = (const float*)d_in[0];
    const void*  ei    = d_in[1];
    const float* W1    = (const float*)d_in[3];
    const float* b1    = (const float*)d_in[4];
    const float* W2    = (const float*)d_in[5];
    const float* b2    = (const float*)d_in[6];
    const float* gamma = (const float*)d_in[7];
    const float* beta  = (const float*)d_in[8];
    float* out = (float*)d_out;

    int N = in_sizes[0] / GIN_H;
    int E = in_sizes[1] / 2;

    const int SMEM = GEMM_SMEM_FLOATS * (int)sizeof(float);  // 80 KB
    cudaFuncSetAttribute(gemm_relu_kernel<false>,
                         cudaFuncAttributeMaxDynamicSharedMemorySize, SMEM);
    cudaFuncSetAttribute(gemm_relu_kernel<true>,
                         cudaFuncAttributeMaxDynamicSharedMemorySize, SMEM);

    int total4 = N * (GIN_H / 4);
    int eb = (E + 255) / 256;
    int nb = (N + SCAN_B - 1) / SCAN_B;

    zero_kernel<<<(N + 255) / 256, 256>>>((const unsigned*)ei, N);
    convert_kernel<<<(total4 + 255) / 256, 256>>>((const float4*)x, total4);
    hist_kernel<<<eb, 256>>>(ei, E);
    scan1_kernel<<<nb, SCAN_B>>>(N);
    scan2_kernel<<<1, 128>>>(nb);
    scan3_kernel<<<(N + 255) / 256, 256>>>(N, E);
    permute_kernel<<<eb, 256>>>(ei, E);

    long long agg_items = (long long)N * 32;
    aggregate_kernel<<<(int)((agg_items + 255) / 256), 256>>>((const float4*)x, N);

    int gemm_blocks = (N + 127) / 128;
    float* h0;  cudaGetSymbolAddress((void**)&h0, g_h0);
    float* h1;  cudaGetSymbolAddress((void**)&h1, g_h1);

    gemm_relu_kernel<false><<<gemm_blocks, 256, SMEM>>>(h0, W1, b1, h1, N);
    gemm_relu_kernel<true ><<<gemm_blocks, 256, SMEM>>>(h1, W2, b2, out, N);

    apply_bn_kernel<<<(total4 + 255) / 256, 256>>>((float4*)out, gamma, beta,
                                                   1.0f / (float)N, total4);
}

// round 7
// speedup vs baseline: 3.7565x; 1.2491x over previous
#include <cuda_runtime.h>
#include <cuda_fp16.h>

// ---------------------------------------------------------------------------
// GINBlock: h = BN(relu( relu((x + segsum(x[src]->dst)) @ W1 + b1) @ W2 + b2 ))
// N=100000, D=H=128, E=3.2M.
// R7: GEMMs moved to tf32 tensor cores (mma.sync m16n8k8). W staged in smem
//     in fragment order (conflict-free LDS.64); A staged per-32k chunk with
//     stride-36 padding (conflict-free A-frag LDS). BN stats fused via
//     shfl reduce + red.v2. Keep: fp16-mirror aggregate, CSR counting sort.
// ---------------------------------------------------------------------------

#define GIN_N_MAX 100000
#define GIN_H 128
#define GIN_E_MAX 3200000
#define SCAN_B 1024
#define SCAN_NB ((GIN_N_MAX + SCAN_B - 1) / SCAN_B)   // 98

__device__ float  g_h0[GIN_N_MAX * GIN_H];
__device__ float  g_h1[GIN_N_MAX * GIN_H];
__device__ __half g_xh[GIN_N_MAX * GIN_H];
__device__ int    g_deg[GIN_N_MAX];
__device__ int    g_off[GIN_N_MAX + 1];
__device__ int    g_cursor[GIN_N_MAX];
__device__ int    g_srcs[GIN_E_MAX];
__device__ int    g_bsum[SCAN_NB];
__device__ int    g_boff[SCAN_NB];
__device__ __align__(16) float g_sum[GIN_H];
__device__ __align__(16) float g_sq[GIN_H];
__device__ int    g_is64;

// zero deg + BN accums; thread 0 sniffs int64-vs-int32 edge_index.
__global__ void zero_kernel(const unsigned* __restrict__ ei, int N) {
    int idx = blockIdx.x * blockDim.x + threadIdx.x;
    if (idx < N) g_deg[idx] = 0;
    if (idx < GIN_H) { g_sum[idx] = 0.f; g_sq[idx] = 0.f; }
    if (idx == 0) {
        int allz = 1;
#pragma unroll
        for (int i = 0; i < 16; i++) allz &= (ei[2 * i + 1] == 0u);
        g_is64 = allz;
    }
}

__global__ void convert_kernel(const float4* __restrict__ x4, int total4) {
    int idx = blockIdx.x * blockDim.x + threadIdx.x;
    if (idx >= total4) return;
    float4 v = x4[idx];
    __half2 a = __floats2half2_rn(v.x, v.y);
    __half2 b = __floats2half2_rn(v.z, v.w);
    uint2 p;
    p.x = *(unsigned*)&a;
    p.y = *(unsigned*)&b;
    ((uint2*)g_xh)[idx] = p;
}

__global__ void hist_kernel(const void* __restrict__ ei, int E) {
    int e = blockIdx.x * blockDim.x + threadIdx.x;
    if (e >= E) return;
    int d = g_is64 ? (int)__ldg(&((const long long*)ei)[E + e])
                   : __ldg(&((const int*)ei)[E + e]);
    atomicAdd(&g_deg[d], 1);
}

// ---- 3-phase exclusive scan ----
__global__ void __launch_bounds__(SCAN_B)
scan1_kernel(int N) {
    __shared__ int sh[SCAN_B];
    int t = threadIdx.x;
    int i = blockIdx.x * SCAN_B + t;
    int v = (i < N) ? g_deg[i] : 0;
    sh[t] = v;
    __syncthreads();
#pragma unroll
    for (int d = 1; d < SCAN_B; d <<= 1) {
        int u = (t >= d) ? sh[t - d] : 0;
        __syncthreads();
        sh[t] += u;
        __syncthreads();
    }
    if (i < N) g_off[i] = sh[t] - v;
    if (t == SCAN_B - 1) g_bsum[blockIdx.x] = sh[t];
}

__global__ void __launch_bounds__(128)
scan2_kernel(int NB) {
    __shared__ int sh[128];
    int t = threadIdx.x;
    int v = (t < NB) ? g_bsum[t] : 0;
    sh[t] = v;
    __syncthreads();
#pragma unroll
    for (int d = 1; d < 128; d <<= 1) {
        int u = (t >= d) ? sh[t - d] : 0;
        __syncthreads();
        sh[t] += u;
        __syncthreads();
    }
    if (t < NB) g_boff[t] = sh[t] - v;
}

__global__ void scan3_kernel(int N, int E) {
    int i = blockIdx.x * blockDim.x + threadIdx.x;
    if (i >= N) return;
    int v = g_off[i] + g_boff[i >> 10];
    g_off[i] = v;
    g_cursor[i] = v;
    if (i == 0) g_off[N] = E;
}

__global__ void permute_kernel(const void* __restrict__ ei, int E) {
    int e = blockIdx.x * blockDim.x + threadIdx.x;
    if (e >= E) return;
    int s, d;
    if (g_is64) {
        const long long* p = (const long long*)ei;
        s = (int)__ldg(&p[e]);
        d = (int)__ldg(&p[E + e]);
    } else {
        const int* p = (const int*)ei;
        s = __ldg(&p[e]);
        d = __ldg(&p[E + e]);
    }
    int pos = atomicAdd(&g_cursor[d], 1);
    g_srcs[pos] = s;
}

// Warp/node gather: fp32 self + fp16-mirror neighbor sum (fp32 accumulate).
__global__ void aggregate_kernel(const float4* __restrict__ x4, int N) {
    int idx = blockIdx.x * blockDim.x + threadIdx.x;
    int node = idx >> 5;
    int lane = idx & 31;
    if (node >= N) return;
    int beg = g_off[node], end = g_off[node + 1];
    float4 acc = x4[node * 32 + lane];
    const uint2* xh = (const uint2*)g_xh;
    int e = beg;
    while (e < end) {
        int cnt = min(32, end - e);
        int myidx = (lane < cnt) ? __ldg(&g_srcs[e + lane]) : 0;
#pragma unroll 4
        for (int j = 0; j < cnt; j++) {
            int s = __shfl_sync(0xffffffffu, myidx, j);
            uint2 p = xh[s * 32 + lane];
            float2 f01 = __half22float2(*(__half2*)&p.x);
            float2 f23 = __half22float2(*(__half2*)&p.y);
            acc.x += f01.x; acc.y += f01.y; acc.z += f23.x; acc.w += f23.y;
        }
        e += cnt;
    }
    ((float4*)g_h0)[node * 32 + lane] = acc;
}

// ---------------------------------------------------------------------------
// tf32 tensor-core GEMM + bias + ReLU (+ BN stats).
// CTA: 256 rows x 128 cols, 512 threads = 16 warps (8 rowgroups x 2 colgroups).
// Warp tile: 32 rows x 64 cols via m16n8k8 (2 row-frags x 8 n-tiles).
// ---------------------------------------------------------------------------
__device__ __forceinline__ unsigned f2tf(float f) {
    unsigned r;
    asm("cvt.rna.tf32.f32 %0, %1;" : "=r"(r) : "f"(f));
    return r;
}
__device__ __forceinline__ void mma_tf32(float* d, const unsigned* a, unsigned b0, unsigned b1) {
    asm("mma.sync.aligned.m16n8k8.row.col.f32.tf32.tf32.f32 "
        "{%0,%1,%2,%3}, {%4,%5,%6,%7}, {%8,%9}, {%0,%1,%2,%3};"
        : "+f"(d[0]), "+f"(d[1]), "+f"(d[2]), "+f"(d[3])
        : "r"(a[0]), "r"(a[1]), "r"(a[2]), "r"(a[3]), "r"(b0), "r"(b1));
}

#define TFG_SMEM_U32 (16384 + 256 * 36)          // Wfrag + As(stride 36)
#define TFG_SMEM_BYTES (TFG_SMEM_U32 * 4)        // 102400

template <bool STATS>
__global__ void __launch_bounds__(512)
gemm_tf32_kernel(const float* __restrict__ A, const float* __restrict__ W,
                 const float* __restrict__ bias, float* __restrict__ out, int N) {
    extern __shared__ unsigned smem_u[];
    unsigned* Wf = smem_u;                  // [ks 0..15][ntg 0..15][lane] x {b0,b1}
    unsigned* As = smem_u + 16384;          // [256][36] tf32

    const int tid = threadIdx.x;
    const int lane = tid & 31;
    const int wid = tid >> 5;
    const int rg = wid >> 1;                // 0..7  (32-row group)
    const int cg = wid & 1;                 // 0..1  (64-col group)
    const int row0 = blockIdx.x * 256;

    // Stage W in fragment order, tf32-converted.
    // slot s: lane=s&31, ntg=(s>>5)&15, ks=s>>9; b0=W[ks*8+l%4][ntg*8+l/4], b1=+4k
#pragma unroll
    for (int i = 0; i < 16; i++) {
        int s = i * 512 + tid;
        int l = s & 31, ntg = (s >> 5) & 15, ks = s >> 9;
        int k = ks * 8 + (l & 3);
        int n = ntg * 8 + (l >> 2);
        unsigned w0 = f2tf(__ldg(&W[k * 128 + n]));
        unsigned w1 = f2tf(__ldg(&W[(k + 4) * 128 + n]));
        *(uint2*)&Wf[s * 2] = make_uint2(w0, w1);
    }

    float d[2][8][4];
#pragma unroll
    for (int f = 0; f < 2; f++)
#pragma unroll
        for (int nt = 0; nt < 8; nt++)
#pragma unroll
            for (int r = 0; r < 4; r++) d[f][nt][r] = 0.f;

    for (int kc = 0; kc < 4; kc++) {
        __syncthreads();   // Wf staged / previous chunk consumed
        // Stage A chunk [256 x 32] (coalesced read, tf32 convert, stride 36)
#pragma unroll
        for (int i = 0; i < 16; i++) {
            int idx = i * 512 + tid;
            int r = idx >> 5, kk = idx & 31;
            float v = 0.f;
            int gr = row0 + r;
            if (gr < N) v = A[gr * 128 + kc * 32 + kk];
            As[r * 36 + kk] = f2tf(v);
        }
        __syncthreads();

#pragma unroll
        for (int ksl = 0; ksl < 4; ksl++) {
            const int ksg = kc * 4 + ksl;
            unsigned a[2][4];
#pragma unroll
            for (int f = 0; f < 2; f++) {
                int r = rg * 32 + f * 16 + (lane >> 2);
                int k = ksl * 8 + (lane & 3);
                a[f][0] = As[r * 36 + k];
                a[f][1] = As[(r + 8) * 36 + k];
                a[f][2] = As[r * 36 + k + 4];
                a[f][3] = As[(r + 8) * 36 + k + 4];
            }
#pragma unroll
            for (int nt = 0; nt < 8; nt++) {
                uint2 b = *(const uint2*)&Wf[((ksg * 16 + cg * 8 + nt) * 32 + lane) * 2];
                mma_tf32(d[0][nt], a[0], b.x, b.y);
                mma_tf32(d[1][nt], a[1], b.x, b.y);
            }
        }
    }

    // Epilogue: bias + relu + store (+ stats)
#pragma unroll
    for (int f = 0; f < 2; f++) {
#pragma unroll
        for (int nt = 0; nt < 8; nt++) {
            int col = cg * 64 + nt * 8 + 2 * (lane & 3);
            int r0 = row0 + rg * 32 + f * 16 + (lane >> 2);
            float b0 = __ldg(&bias[col]);
            float b1 = __ldg(&bias[col + 1]);
            float v0 = fmaxf(d[f][nt][0] + b0, 0.f);
            float v1 = fmaxf(d[f][nt][1] + b1, 0.f);
            float v2 = fmaxf(d[f][nt][2] + b0, 0.f);
            float v3 = fmaxf(d[f][nt][3] + b1, 0.f);
            bool ok0 = (r0 < N), ok1 = (r0 + 8 < N);
            if (ok0) *(float2*)&out[r0 * 128 + col] = make_float2(v0, v1);
            if (ok1) *(float2*)&out[(r0 + 8) * 128 + col] = make_float2(v2, v3);
            if (STATS) {
                float s0 = (ok0 ? v0 : 0.f) + (ok1 ? v2 : 0.f);
                float s1 = (ok0 ? v1 : 0.f) + (ok1 ? v3 : 0.f);
                float q0 = (ok0 ? v0 * v0 : 0.f) + (ok1 ? v2 * v2 : 0.f);
                float q1 = (ok0 ? v1 * v1 : 0.f) + (ok1 ? v3 * v3 : 0.f);
#pragma unroll
                for (int m = 16; m >= 4; m >>= 1) {
                    s0 += __shfl_xor_sync(0xffffffffu, s0, m);
                    s1 += __shfl_xor_sync(0xffffffffu, s1, m);
                    q0 += __shfl_xor_sync(0xffffffffu, q0, m);
                    q1 += __shfl_xor_sync(0xffffffffu, q1, m);
                }
                if (lane < 4) {
                    asm volatile("red.global.add.v2.f32 [%0], {%1, %2};"
                                 :: "l"(&g_sum[col]), "f"(s0), "f"(s1) : "memory");
                    asm volatile("red.global.add.v2.f32 [%0], {%1, %2};"
                                 :: "l"(&g_sq[col]), "f"(q0), "f"(q1) : "memory");
                }
            }
        }
    }
}

// BN apply; per-block recompute of scale/shift from global sums.
__global__ void apply_bn_kernel(float4* __restrict__ out,
                                const float* __restrict__ gamma,
                                const float* __restrict__ beta,
                                float invN, int total4) {
    __shared__ float s_scale[GIN_H], s_shift[GIN_H];
    int t = threadIdx.x;
    if (t < GIN_H) {
        float mean = g_sum[t] * invN;
        float var = fmaf(-mean, mean, g_sq[t] * invN);
        float sc = gamma[t] * rsqrtf(var + 1e-5f);
        s_scale[t] = sc;
        s_shift[t] = fmaf(-mean, sc, beta[t]);
    }
    __syncthreads();
    int idx = blockIdx.x * blockDim.x + t;
    if (idx >= total4) return;
    int c = (idx & 31) * 4;
    float4 v = out[idx];
    v.x = fmaf(v.x, s_scale[c + 0], s_shift[c + 0]);
    v.y = fmaf(v.y, s_scale[c + 1], s_shift[c + 1]);
    v.z = fmaf(v.z, s_scale[c + 2], s_shift[c + 2]);
    v.w = fmaf(v.w, s_scale[c + 3], s_shift[c + 3]);
    out[idx] = v;
}

// ---------------------------------------------------------------------------
// Inputs: x, edge_index, edge_attr, W1, b1, W2, b2, gamma, beta
// ---------------------------------------------------------------------------
extern "C" void kernel_launch(void* const* d_in, const int* in_sizes, int n_in,
                              void* d_out, int out_size) {
    const float* x     = (const float*)d_in[0];
    const void*  ei    = d_in[1];
    const float* W1    = (const float*)d_in[3];
    const float* b1    = (const float*)d_in[4];
    const float* W2    = (const float*)d_in[5];
    const float* b2    = (const float*)d_in[6];
    const float* gamma = (const float*)d_in[7];
    const float* beta  = (const float*)d_in[8];
    float* out = (float*)d_out;

    int N = in_sizes[0] / GIN_H;
    int E = in_sizes[1] / 2;

    cudaFuncSetAttribute(gemm_tf32_kernel<false>,
                         cudaFuncAttributeMaxDynamicSharedMemorySize, TFG_SMEM_BYTES);
    cudaFuncSetAttribute(gemm_tf32_kernel<true>,
                         cudaFuncAttributeMaxDynamicSharedMemorySize, TFG_SMEM_BYTES);

    int total4 = N * (GIN_H / 4);
    int eb = (E + 255) / 256;
    int nb = (N + SCAN_B - 1) / SCAN_B;

    zero_kernel<<<(N + 255) / 256, 256>>>((const unsigned*)ei, N);
    convert_kernel<<<(total4 + 255) / 256, 256>>>((const float4*)x, total4);
    hist_kernel<<<eb, 256>>>(ei, E);
    scan1_kernel<<<nb, SCAN_B>>>(N);
    scan2_kernel<<<1, 128>>>(nb);
    scan3_kernel<<<(N + 255) / 256, 256>>>(N, E);
    permute_kernel<<<eb, 256>>>(ei, E);

    long long agg_items = (long long)N * 32;
    aggregate_kernel<<<(int)((agg_items + 255) / 256), 256>>>((const float4*)x, N);

    int gemm_blocks = (N + 255) / 256;
    float* h0;  cudaGetSymbolAddress((void**)&h0, g_h0);
    float* h1;  cudaGetSymbolAddress((void**)&h1, g_h1);

    gemm_tf32_kernel<false><<<gemm_blocks, 512, TFG_SMEM_BYTES>>>(h0, W1, b1, h1, N);
    gemm_tf32_kernel<true ><<<gemm_blocks, 512, TFG_SMEM_BYTES>>>(h1, W2, b2, out, N);

    apply_bn_kernel<<<(total4 + 255) / 256, 256>>>((float4*)out, gamma, beta,
                                                   1.0f / (float)N, total4);
}